// round 9
// baseline (speedup 1.0000x reference)
#include <cuda_runtime.h>
#include <cuda_bf16.h>
#include <cstdint>
#include <math_constants.h>

// Problem constants
#define BB 16
#define CC 8
#define TT 4096
#define KK 64
#define LL 128
#define TP (TT - LL + 1)        // 3969 valid sliding positions
#define TCHUNK 128              // t' per CTA
#define NCHUNK 32               // ceil(3969/128)
#define NSTEP 8                 // 128 / 16 k per bf16 mma

typedef unsigned int u32;

// Pre-packed B fragments [step][nt][lane] = (b0,b1) and shapelet norms
__device__ uint2 gB[NSTEP * 8 * 32];    // 16 KB
__device__ float gOffs[KK];

__device__ __forceinline__ u32 pack_bf16(float a, float b) {
    __nv_bfloat162 h = __floats2bfloat162_rn(a, b);
    return *(u32*)&h;
}

__device__ __forceinline__ u32 smem_u32(const void* p) {
    u32 a;
    asm("{ .reg .u64 t; cvta.to.shared.u64 t, %1; cvt.u32.u64 %0, t; }" : "=r"(a) : "l"(p));
    return a;
}

__device__ __forceinline__ void cp16(u32 saddr, const void* gaddr) {
    asm volatile("cp.async.cg.shared.global [%0], [%1], 16;" :: "r"(saddr), "l"(gaddr));
}

__device__ __forceinline__ void mma_bf16(float* c, u32 a0, u32 a1, u32 a2, u32 a3,
                                         u32 b0, u32 b1) {
    asm volatile(
        "mma.sync.aligned.m16n8k16.row.col.f32.bf16.bf16.f32 "
        "{%0,%1,%2,%3}, {%4,%5,%6,%7}, {%8,%9}, {%0,%1,%2,%3};"
        : "+f"(c[0]), "+f"(c[1]), "+f"(c[2]), "+f"(c[3])
        : "r"(a0), "r"(a1), "r"(a2), "r"(a3), "r"(b0), "r"(b1));
}

// Prep: pack B fragments, shapelet norms, init out. grid = 8 CTAs x 256.
__global__ void prep_kernel(const float* __restrict__ S, int* __restrict__ out) {
    const int tid  = threadIdx.x;
    const int wid  = tid >> 5;
    const int lane = tid & 31;
    const int g    = lane >> 2;
    const int t    = lane & 3;
    const int cta  = blockIdx.x;         // 0..7

    // B fragments: this CTA covers nt = cta; warp wid covers step s = wid.
    {
        int nt = cta, s = wid;
        int row = nt * 8 + g;
        const float2* Sr = (const float2*)(S + row * LL);
        float2 p = Sr[s * 8 + t];
        float2 q = Sr[s * 8 + 4 + t];
        uint2 v;
        v.x = pack_bf16(p.x, p.y);
        v.y = pack_bf16(q.x, q.y);
        gB[s * 256 + nt * 32 + lane] = v;
    }

    // Norms: warp wid computes row r = cta*8 + wid
    {
        int r = cta * 8 + wid;
        const float4* Sr = (const float4*)(S + r * LL);
        float4 v = Sr[lane];
        float ns = v.x * v.x + v.y * v.y + v.z * v.z + v.w * v.w;
        #pragma unroll
        for (int o = 16; o > 0; o >>= 1)
            ns += __shfl_xor_sync(0xffffffffu, ns, o);
        if (lane == 0) gOffs[r] = (float)CC * ns;
    }

    // Init out: 1024 ints / 8 CTAs = 128 each
    if (tid < 128) out[cta * 128 + tid] = 0x7F800000;
}

__global__ __launch_bounds__(256, 3)
void shapelet_bf16_kernel(const float* __restrict__ X,
                          float* __restrict__ out) {
    __shared__ uint2 sB[NSTEP * 8 * 32];     // 16 KB, filled by cp.async
    __shared__ float offs[KK];               // filled by cp.async
    __shared__ float xs[TCHUNK + LL + 4];    // channel-sum (f32); zero pad
    __shared__ float xq[TCHUNK + LL];        // channel-sum of x^2
    __shared__ u32   ea[TCHUNK + 4];         // half2(xs[2j], xs[2j+1])
    __shared__ u32   oa[TCHUNK + 4];         // half2(xs[2j+1], xs[2j+2])
    __shared__ float pscan[TCHUNK + LL];     // per-32-seg inclusive scans of xq
    __shared__ float segt[8];                // segment totals
    __shared__ float ws[TCHUNK];             // window sums (+inf past TP)
    __shared__ float red[8 * KK];            // per-warp partial mins

    const int tid  = threadIdx.x;
    const int wid  = tid >> 5;
    const int lane = tid & 31;
    const int g    = lane >> 2;              // groupID 0..7
    const int t    = lane & 3;               // threadID_in_group 0..3
    const int b    = blockIdx.y;
    const int tbase = blockIdx.x * TCHUNK;

    // ---- Async fetch of pre-packed B fragments + norms ----
    {
        u32 sb = smem_u32(sB) + tid * 64;
        const char* gb = (const char*)gB + tid * 64;
        #pragma unroll
        for (int i = 0; i < 4; i++) cp16(sb + i * 16, gb + i * 16);
        if (tid < 16) cp16(smem_u32(offs) + tid * 16, (const char*)gOffs + tid * 16);
        asm volatile("cp.async.commit_group;" ::: "memory");
    }

    // ---- Prologue 2: channel sums, one t per thread (overlaps cp.async) ----
    {
        int tg = tbase + tid;
        float sm = 0.f, sq = 0.f;
        if (tg < TT) {
            #pragma unroll
            for (int c = 0; c < CC; c++) {
                float v = X[((b * CC + c) << 12) + tg];
                sm += v; sq += v * v;
            }
        }
        xs[tid] = sm; xq[tid] = sq;
    }
    if (tid < 4) xs[TCHUNK + LL + tid] = 0.f;
    asm volatile("cp.async.wait_group 0;" ::: "memory");
    __syncthreads();

    // ---- Prologue 3a: parity-aligned bf16 pair arrays for A fragments ----
    if (tid < TCHUNK + 2) {
        float x0 = xs[2 * tid], x1 = xs[2 * tid + 1], x2 = xs[2 * tid + 2];
        ea[tid] = pack_bf16(x0, x1);
        oa[tid] = pack_bf16(x1, x2);
    }

    // ---- Prologue 3b: segmented scan of xq (8 segments of 32, 1/warp) ----
    {
        float v = xq[wid * 32 + lane];
        #pragma unroll
        for (int o = 1; o < 32; o <<= 1) {
            float u = __shfl_up_sync(0xffffffffu, v, o);
            if (lane >= o) v += u;
        }
        pscan[wid * 32 + lane] = v;
        if (lane == 31) segt[wid] = v;
    }
    __syncthreads();

    // ---- ws[t'] = sum_{i=t'}^{t'+127} xq[i], via segment decomposition ----
    if (tid < TCHUNK) {
        int q = tid >> 5, r = tid & 31;
        float suf  = segt[q] - (pscan[tid] - xq[tid]);
        float mid  = segt[q + 1] + segt[q + 2] + segt[q + 3];
        float head = (r == 0) ? 0.f : pscan[(q + 4) * 32 + r - 1];
        float w = suf + mid + head;
        ws[tid] = (tbase + tid < TP) ? w : CUDART_INF_F;
    }
    __syncthreads();

    // ---- Main: warp wid computes m-tile rows [wid*16, wid*16+16), all 64 k ----
    // A fragments (Toeplitz, a1==a2): a0=v(i0+16s), a1=a2=v(i0+16s+8), a3=v(i0+16s+16)
    const u32* ap = (g & 1) ? oa : ea;
    const int i0 = wid * 16 + g + 2 * t;
    const int j0 = i0 >> 1;
    u32 r0 = ap[j0];
    u32 r1 = ap[j0 + 4];

    float acc[8][4];
    #pragma unroll
    for (int nt = 0; nt < 8; nt++)
        #pragma unroll
        for (int j = 0; j < 4; j++)
            acc[nt][j] = 0.f;

    #pragma unroll
    for (int s = 0; s < NSTEP; s++) {
        uint2 bv[8];
        const uint2* bp = sB + s * 256 + lane;
        #pragma unroll
        for (int nt = 0; nt < 8; nt++) bv[nt] = bp[nt * 32];
        u32 r2 = ap[j0 + 8 * s + 8];
        #pragma unroll
        for (int nt = 0; nt < 8; nt++)
            mma_bf16(acc[nt], r0, r1, r1, r2, bv[nt].x, bv[nt].y);
        r0 = r2;
        if (s < NSTEP - 1) r1 = ap[j0 + 8 * s + 12];
    }

    // ---- Epilogue: dist = ws - 2*corr, min over this warp's 16 rows ----
    float w0 = ws[wid * 16 + g];
    float w1 = ws[wid * 16 + g + 8];
    float m16[16];
    #pragma unroll
    for (int nt = 0; nt < 8; nt++) {
        #pragma unroll
        for (int j = 0; j < 2; j++) {
            float v0 = fmaf(-2.f, acc[nt][j],     w0);
            float v1 = fmaf(-2.f, acc[nt][2 + j], w1);
            m16[nt * 2 + j] = fminf(v0, v1);
        }
    }
    // reduce across g (lane bits 2..4)
    #pragma unroll
    for (int i = 0; i < 16; i++) {
        m16[i] = fminf(m16[i], __shfl_xor_sync(0xffffffffu, m16[i], 4));
        m16[i] = fminf(m16[i], __shfl_xor_sync(0xffffffffu, m16[i], 8));
        m16[i] = fminf(m16[i], __shfl_xor_sync(0xffffffffu, m16[i], 16));
    }
    if (g == 0) {
        #pragma unroll
        for (int nt = 0; nt < 8; nt++) {
            red[wid * KK + nt * 8 + 2 * t + 0] = m16[nt * 2 + 0];
            red[wid * KK + nt * 8 + 2 * t + 1] = m16[nt * 2 + 1];
        }
    }
    __syncthreads();

    if (tid < KK) {
        float m = red[tid];
        #pragma unroll
        for (int w = 1; w < 8; w++) m = fminf(m, red[w * KK + tid]);
        m += offs[tid];
        atomicMin((int*)&out[b * KK + tid], __float_as_int(m));
    }
}

extern "C" void kernel_launch(void* const* d_in, const int* in_sizes, int n_in,
                              void* d_out, int out_size) {
    const float* X = (const float*)d_in[0];   // (16, 8, 4096) f32
    const float* S = (const float*)d_in[1];   // (64, 128) f32
    float* out = (float*)d_out;               // (16, 64) f32

    prep_kernel<<<8, 256>>>(S, (int*)out);
    dim3 grid(NCHUNK, BB);
    shapelet_bf16_kernel<<<grid, 256>>>(X, out);
}

// round 10
// speedup vs baseline: 1.0745x; 1.0745x over previous
#include <cuda_runtime.h>
#include <cuda_bf16.h>
#include <cstdint>
#include <math_constants.h>

// Problem constants
#define BB 16
#define CC 8
#define TT 4096
#define KK 64
#define LL 128
#define TP (TT - LL + 1)        // 3969 valid sliding positions
#define TCHUNK 256              // t' per CTA
#define NCHUNK 16               // ceil(3969/256)
#define NSTEP 8                 // 128 / 16 k per bf16 mma

typedef unsigned int u32;

// Pre-packed B fragments [step][nt][lane] = (b0,b1) and shapelet norms
__device__ uint2 gB[NSTEP * 8 * 32];    // 16 KB
__device__ float gOffs[KK];

__device__ __forceinline__ u32 pack_bf16(float a, float b) {
    __nv_bfloat162 h = __floats2bfloat162_rn(a, b);
    return *(u32*)&h;
}

__device__ __forceinline__ u32 smem_u32(const void* p) {
    u32 a;
    asm("{ .reg .u64 t; cvta.to.shared.u64 t, %1; cvt.u32.u64 %0, t; }" : "=r"(a) : "l"(p));
    return a;
}

__device__ __forceinline__ void cp16(u32 saddr, const void* gaddr) {
    asm volatile("cp.async.cg.shared.global [%0], [%1], 16;" :: "r"(saddr), "l"(gaddr));
}

__device__ __forceinline__ void mma_bf16(float* c, u32 a0, u32 a1, u32 a2, u32 a3,
                                         u32 b0, u32 b1) {
    asm volatile(
        "mma.sync.aligned.m16n8k16.row.col.f32.bf16.bf16.f32 "
        "{%0,%1,%2,%3}, {%4,%5,%6,%7}, {%8,%9}, {%0,%1,%2,%3};"
        : "+f"(c[0]), "+f"(c[1]), "+f"(c[2]), "+f"(c[3])
        : "r"(a0), "r"(a1), "r"(a2), "r"(a3), "r"(b0), "r"(b1));
}

// Prep: pack B fragments, shapelet norms, init out. grid = 8 CTAs x 256.
__global__ void prep_kernel(const float* __restrict__ S, int* __restrict__ out) {
    const int tid  = threadIdx.x;
    const int wid  = tid >> 5;
    const int lane = tid & 31;
    const int g    = lane >> 2;
    const int t    = lane & 3;
    const int cta  = blockIdx.x;         // 0..7

    // B fragments: this CTA covers nt = cta; warp wid covers step s = wid.
    {
        int nt = cta, s = wid;
        int row = nt * 8 + g;
        const float2* Sr = (const float2*)(S + row * LL);
        float2 p = Sr[s * 8 + t];
        float2 q = Sr[s * 8 + 4 + t];
        uint2 v;
        v.x = pack_bf16(p.x, p.y);
        v.y = pack_bf16(q.x, q.y);
        gB[s * 256 + nt * 32 + lane] = v;
    }

    // Norms: warp wid computes row r = cta*8 + wid
    {
        int r = cta * 8 + wid;
        const float4* Sr = (const float4*)(S + r * LL);
        float4 v = Sr[lane];
        float ns = v.x * v.x + v.y * v.y + v.z * v.z + v.w * v.w;
        #pragma unroll
        for (int o = 16; o > 0; o >>= 1)
            ns += __shfl_xor_sync(0xffffffffu, ns, o);
        if (lane == 0) gOffs[r] = (float)CC * ns;
    }

    // Init out: 1024 ints / 8 CTAs = 128 each
    if (tid < 128) out[cta * 128 + tid] = 0x7F800000;

    // PDL: make writes visible, then release dependent grid
    __threadfence();
    asm volatile("griddepcontrol.launch_dependents;" ::: "memory");
}

__global__ __launch_bounds__(256, 2)
void shapelet_bf16_kernel(const float* __restrict__ X,
                          float* __restrict__ out) {
    __shared__ uint2 sB[NSTEP * 8 * 32];   // 16 KB, filled by cp.async
    __shared__ float offs[KK];             // filled by cp.async
    __shared__ float xs[TCHUNK + LL + 2];  // channel-sum (f32); pad
    __shared__ float xq[TCHUNK + LL];      // channel-sum of x^2
    __shared__ u32   ea[200];              // half2(xs[2j], xs[2j+1])
    __shared__ u32   oa[200];              // half2(xs[2j+1], xs[2j+2])
    __shared__ float pscan[TCHUNK + LL];   // per-32-seg inclusive scans of xq
    __shared__ float segt[12];             // segment totals
    __shared__ float ws[TCHUNK];           // window sums (+inf past TP)
    __shared__ float red[8 * KK];          // per-warp partial mins

    const int tid  = threadIdx.x;
    const int wid  = tid >> 5;
    const int lane = tid & 31;
    const int g    = lane >> 2;            // groupID 0..7
    const int t    = lane & 3;             // threadID_in_group 0..3
    const int b    = blockIdx.y;
    const int tbase = blockIdx.x * TCHUNK;

    // ---- Issue X loads FIRST (independent of prep kernel) ----
    // position 1: j = tid (always in range: tbase+tid <= 3840+255 = 4095)
    // position 2: j = 256+tid for tid < 128 (may exceed TT on last chunk)
    float va[CC], vb[CC];
    const bool has2 = tid < 128;
    const bool v2ok = has2 && (tbase + 256 + tid < TT);
    {
        const float* Xb = X + ((size_t)b * CC << 12) + tbase;
        #pragma unroll
        for (int c = 0; c < CC; c++) va[c] = Xb[(c << 12) + tid];
        #pragma unroll
        for (int c = 0; c < CC; c++) vb[c] = v2ok ? Xb[(c << 12) + 256 + tid] : 0.f;
    }

    // ---- PDL: wait for prep's gB/gOffs/out-init, then fetch async ----
    asm volatile("griddepcontrol.wait;" ::: "memory");
    {
        u32 sb = smem_u32(sB) + tid * 64;
        const char* gb = (const char*)gB + tid * 64;
        #pragma unroll
        for (int i = 0; i < 4; i++) cp16(sb + i * 16, gb + i * 16);
        if (tid < 16) cp16(smem_u32(offs) + tid * 16, (const char*)gOffs + tid * 16);
        asm volatile("cp.async.commit_group;" ::: "memory");
    }

    // ---- Channel sums from preloaded registers ----
    {
        float sm = 0.f, sq = 0.f;
        #pragma unroll
        for (int c = 0; c < CC; c++) { sm += va[c]; sq += va[c] * va[c]; }
        xs[tid] = sm; xq[tid] = sq;
        if (has2) {
            float sm2 = 0.f, sq2 = 0.f;
            #pragma unroll
            for (int c = 0; c < CC; c++) { sm2 += vb[c]; sq2 += vb[c] * vb[c]; }
            xs[256 + tid] = sm2; xq[256 + tid] = sq2;
        }
    }
    if (tid == 0) { xs[TCHUNK + LL] = 0.f; xs[TCHUNK + LL + 1] = 0.f; }
    __syncthreads();

    // ---- Prologue 3a: parity-aligned bf16 pair arrays for A fragments ----
    if (tid < 192) {
        float x0 = xs[2 * tid], x1 = xs[2 * tid + 1], x2 = xs[2 * tid + 2];
        ea[tid] = pack_bf16(x0, x1);
        oa[tid] = pack_bf16(x1, x2);
    }

    // ---- Prologue 3b: segmented scan of xq; extra 4 segs on warps 4-7 ----
    {
        #pragma unroll
        for (int pass = 0; pass < 2; pass++) {
            int seg = (pass == 0) ? wid : (wid + 4);
            if (pass == 0 || wid >= 4) {
                float v = xq[seg * 32 + lane];
                #pragma unroll
                for (int o = 1; o < 32; o <<= 1) {
                    float u = __shfl_up_sync(0xffffffffu, v, o);
                    if (lane >= o) v += u;
                }
                pscan[seg * 32 + lane] = v;
                if (lane == 31) segt[seg] = v;
            }
        }
    }
    __syncthreads();

    // ---- ws[t'] = sum_{i=t'}^{t'+127} xq[i], via segment decomposition ----
    {
        int q = tid >> 5, r = tid & 31;
        float suf  = segt[q] - (pscan[tid] - xq[tid]);
        float mid  = segt[q + 1] + segt[q + 2] + segt[q + 3];
        float head = (r == 0) ? 0.f : pscan[(q + 4) * 32 + r - 1];
        float w = suf + mid + head;
        ws[tid] = (tbase + tid < TP) ? w : CUDART_INF_F;
    }
    asm volatile("cp.async.wait_group 0;" ::: "memory");
    __syncthreads();

    // ---- Main: warp wid computes rows [wid*32, wid*32+32), all 64 k ----
    // A fragments (Toeplitz, a1==a2): a0=v(i0+16s), a1=a2=v(i0+16s+8), a3=v(i0+16s+16)
    const u32* ap = (g & 1) ? oa : ea;
    int j0[2]; u32 r0[2], r1[2];
    #pragma unroll
    for (int m = 0; m < 2; m++) {
        int i0 = wid * 32 + m * 16 + g + 2 * t;
        j0[m] = i0 >> 1;
        r0[m] = ap[j0[m]];
        r1[m] = ap[j0[m] + 4];
    }

    float acc[2][8][4];
    #pragma unroll
    for (int m = 0; m < 2; m++)
        #pragma unroll
        for (int nt = 0; nt < 8; nt++)
            #pragma unroll
            for (int j = 0; j < 4; j++)
                acc[m][nt][j] = 0.f;

    // Double-buffered B fragments
    uint2 bvA[8], bvB[8];
    {
        const uint2* bp = sB + lane;
        #pragma unroll
        for (int nt = 0; nt < 8; nt++) bvA[nt] = bp[nt * 32];
    }

    #pragma unroll
    for (int s = 0; s < NSTEP; s++) {
        uint2* cur = (s & 1) ? bvB : bvA;
        uint2* nxt = (s & 1) ? bvA : bvB;
        if (s < NSTEP - 1) {
            const uint2* bp = sB + (s + 1) * 256 + lane;
            #pragma unroll
            for (int nt = 0; nt < 8; nt++) nxt[nt] = bp[nt * 32];
        }
        #pragma unroll
        for (int m = 0; m < 2; m++) {
            u32 r2 = ap[j0[m] + 8 * s + 8];
            #pragma unroll
            for (int nt = 0; nt < 8; nt++)
                mma_bf16(acc[m][nt], r0[m], r1[m], r1[m], r2, cur[nt].x, cur[nt].y);
            r0[m] = r2;
            if (s < NSTEP - 1) r1[m] = ap[j0[m] + 8 * s + 12];
        }
    }

    // ---- Epilogue: dist = ws - 2*corr, min over this warp's 32 rows ----
    float m16[16];
    {
        float w0 = ws[wid * 32 + g];
        float w1 = ws[wid * 32 + g + 8];
        #pragma unroll
        for (int nt = 0; nt < 8; nt++) {
            #pragma unroll
            for (int j = 0; j < 2; j++) {
                float v0 = fmaf(-2.f, acc[0][nt][j],     w0);
                float v1 = fmaf(-2.f, acc[0][nt][2 + j], w1);
                m16[nt * 2 + j] = fminf(v0, v1);
            }
        }
        float w2 = ws[wid * 32 + 16 + g];
        float w3 = ws[wid * 32 + 16 + g + 8];
        #pragma unroll
        for (int nt = 0; nt < 8; nt++) {
            #pragma unroll
            for (int j = 0; j < 2; j++) {
                float v0 = fmaf(-2.f, acc[1][nt][j],     w2);
                float v1 = fmaf(-2.f, acc[1][nt][2 + j], w3);
                m16[nt * 2 + j] = fminf(m16[nt * 2 + j], fminf(v0, v1));
            }
        }
    }
    // reduce across g (lane bits 2..4)
    #pragma unroll
    for (int i = 0; i < 16; i++) {
        m16[i] = fminf(m16[i], __shfl_xor_sync(0xffffffffu, m16[i], 4));
        m16[i] = fminf(m16[i], __shfl_xor_sync(0xffffffffu, m16[i], 8));
        m16[i] = fminf(m16[i], __shfl_xor_sync(0xffffffffu, m16[i], 16));
    }
    if (g == 0) {
        #pragma unroll
        for (int nt = 0; nt < 8; nt++) {
            red[wid * KK + nt * 8 + 2 * t + 0] = m16[nt * 2 + 0];
            red[wid * KK + nt * 8 + 2 * t + 1] = m16[nt * 2 + 1];
        }
    }
    __syncthreads();

    if (tid < KK) {
        float m = red[tid];
        #pragma unroll
        for (int w = 1; w < 8; w++) m = fminf(m, red[w * KK + tid]);
        m += offs[tid];
        atomicMin((int*)&out[b * KK + tid], __float_as_int(m));
    }
}

extern "C" void kernel_launch(void* const* d_in, const int* in_sizes, int n_in,
                              void* d_out, int out_size) {
    const float* X = (const float*)d_in[0];   // (16, 8, 4096) f32
    const float* S = (const float*)d_in[1];   // (64, 128) f32
    float* out = (float*)d_out;               // (16, 64) f32

    prep_kernel<<<8, 256>>>(S, (int*)out);

    dim3 grid(NCHUNK, BB);
    cudaLaunchConfig_t cfg = {};
    cfg.gridDim = grid;
    cfg.blockDim = dim3(256, 1, 1);
    cfg.dynamicSmemBytes = 0;
    cfg.stream = 0;
    cudaLaunchAttribute attr[1];
    attr[0].id = cudaLaunchAttributeProgrammaticStreamSerialization;
    attr[0].val.programmaticStreamSerializationAllowed = 1;
    cfg.attrs = attr;
    cfg.numAttrs = 1;
    cudaError_t err = cudaLaunchKernelEx(&cfg, shapelet_bf16_kernel, X, out);
    if (err != cudaSuccess) {
        // PDL not supported in this context: plain launch (griddepcontrol ops are no-ops)
        shapelet_bf16_kernel<<<grid, 256>>>(X, out);
    }
}

// round 11
// speedup vs baseline: 1.2586x; 1.1713x over previous
#include <cuda_runtime.h>
#include <cuda_bf16.h>
#include <cstdint>
#include <math_constants.h>

// Problem constants
#define BB 16
#define CC 8
#define TT 4096
#define KK 64
#define LL 128
#define TP (TT - LL + 1)        // 3969 valid sliding positions
#define TCHUNK 256              // t' per CTA
#define NCHUNK 16               // ceil(3969/256)
#define NSTEP 8                 // 128 / 16 k per bf16 mma
#define NMT 16                  // m-tiles per CTA (256 rows / 16)
#define NDIAG 23                // u = m + s ranges 0..22

typedef unsigned int u32;

// Pre-packed B fragments [step][nt][lane] = (b0,b1) and shapelet norms
__device__ uint2 gB[NSTEP * 8 * 32];    // 16 KB
__device__ float gOffs[KK];

__device__ __forceinline__ u32 pack_bf16(float a, float b) {
    __nv_bfloat162 h = __floats2bfloat162_rn(a, b);
    return *(u32*)&h;
}

__device__ __forceinline__ void mma_bf16(float* c, u32 a0, u32 a1, u32 a2, u32 a3,
                                         u32 b0, u32 b1) {
    asm volatile(
        "mma.sync.aligned.m16n8k16.row.col.f32.bf16.bf16.f32 "
        "{%0,%1,%2,%3}, {%4,%5,%6,%7}, {%8,%9}, {%0,%1,%2,%3};"
        : "+f"(c[0]), "+f"(c[1]), "+f"(c[2]), "+f"(c[3])
        : "r"(a0), "r"(a1), "r"(a2), "r"(a3), "r"(b0), "r"(b1));
}

// Prep: pack B fragments, shapelet norms, init out. grid = 8 CTAs x 256.
__global__ void prep_kernel(const float* __restrict__ S, int* __restrict__ out) {
    const int tid  = threadIdx.x;
    const int wid  = tid >> 5;
    const int lane = tid & 31;
    const int g    = lane >> 2;
    const int t    = lane & 3;
    const int cta  = blockIdx.x;         // 0..7

    // B fragments: this CTA covers nt = cta; warp wid covers step s = wid.
    {
        int nt = cta, s = wid;
        int row = nt * 8 + g;
        const float2* Sr = (const float2*)(S + row * LL);
        float2 p = Sr[s * 8 + t];
        float2 q = Sr[s * 8 + 4 + t];
        uint2 v;
        v.x = pack_bf16(p.x, p.y);
        v.y = pack_bf16(q.x, q.y);
        gB[s * 256 + nt * 32 + lane] = v;
    }

    // Norms: warp wid computes row r = cta*8 + wid
    {
        int r = cta * 8 + wid;
        const float4* Sr = (const float4*)(S + r * LL);
        float4 v = Sr[lane];
        float ns = v.x * v.x + v.y * v.y + v.z * v.z + v.w * v.w;
        #pragma unroll
        for (int o = 16; o > 0; o >>= 1)
            ns += __shfl_xor_sync(0xffffffffu, ns, o);
        if (lane == 0) gOffs[r] = (float)CC * ns;
    }

    // Init out: 1024 ints / 8 CTAs = 128 each
    if (tid < 128) out[cta * 128 + tid] = 0x7F800000;
}

__global__ __launch_bounds__(256, 2)
void shapelet_bf16_kernel(const float* __restrict__ X,
                          float* __restrict__ out) {
    __shared__ float xs[TCHUNK + LL + 2];  // channel-sum (f32); zero pad
    __shared__ float xq[TCHUNK + LL];      // channel-sum of x^2
    __shared__ u32   ea[200];              // bf16x2(xs[2j], xs[2j+1])
    __shared__ u32   oa[200];              // bf16x2(xs[2j+1], xs[2j+2])
    __shared__ float pscan[TCHUNK + LL];   // per-32-seg inclusive scans of xq
    __shared__ float segt[12];             // segment totals
    __shared__ float ws[TCHUNK];           // window sums (+inf past TP)

    const int tid  = threadIdx.x;
    const int wid  = tid >> 5;             // warp = n-tile (8 warps, 8 nt)
    const int lane = tid & 31;
    const int g    = lane >> 2;            // groupID 0..7
    const int t    = lane & 3;             // threadID_in_group 0..3
    const int b    = blockIdx.y;
    const int tbase = blockIdx.x * TCHUNK;

    // ---- Early LDGs: B fragments for this warp's nt (L2-resident) + norms ----
    uint2 Bv[NSTEP];
    #pragma unroll
    for (int s = 0; s < NSTEP; s++) Bv[s] = gB[s * 256 + wid * 32 + lane];
    const float offs0 = gOffs[wid * 8 + 2 * t];
    const float offs1 = gOffs[wid * 8 + 2 * t + 1];

    // ---- Prologue: channel sums for t in [tbase, tbase+384) ----
    for (int j = tid; j < TCHUNK + LL; j += 256) {
        int tg = tbase + j;
        float sm = 0.f, sq = 0.f;
        if (tg < TT) {
            #pragma unroll
            for (int c = 0; c < CC; c++) {
                float v = X[((b * CC + c) << 12) + tg];
                sm += v; sq += v * v;
            }
        }
        xs[j] = sm; xq[j] = sq;
    }
    if (tid == 0) { xs[TCHUNK + LL] = 0.f; xs[TCHUNK + LL + 1] = 0.f; }
    __syncthreads();

    // ---- Parity-aligned bf16 pair arrays for A fragments ----
    if (tid < 192) {
        float x0 = xs[2 * tid], x1 = xs[2 * tid + 1], x2 = xs[2 * tid + 2];
        ea[tid] = pack_bf16(x0, x1);
        oa[tid] = pack_bf16(x1, x2);
    }

    // ---- Segmented scan of xq (12 segments of 32) ----
    for (int seg = wid; seg < 12; seg += 8) {
        float v = xq[seg * 32 + lane];
        #pragma unroll
        for (int o = 1; o < 32; o <<= 1) {
            float u = __shfl_up_sync(0xffffffffu, v, o);
            if (lane >= o) v += u;
        }
        pscan[seg * 32 + lane] = v;
        if (lane == 31) segt[seg] = v;
    }
    __syncthreads();

    // ---- ws[t'] = sum_{i=t'}^{t'+127} xq[i], via segment decomposition ----
    {
        int q = tid >> 5, r = tid & 31;
        float suf  = segt[q] - (pscan[tid] - xq[tid]);
        float mid  = segt[q + 1] + segt[q + 2] + segt[q + 3];
        float head = (r == 0) ? 0.f : pscan[(q + 4) * 32 + r - 1];
        float w = suf + mid + head;
        ws[tid] = (tbase + tid < TP) ? w : CUDART_INF_F;
    }
    __syncthreads();

    // ---- Main: diagonal-order GEMM. Warp owns nt=wid, all 16 m-tiles. ----
    // A[r][c] = xs[r + c] (Toeplitz). frag(m,s) = (Av[2u], Av[2u+1], Av[2u+1],
    // Av[2u+2]) with u = m+s, where Av[j] = ap[j00 + 4j].
    const u32* ap = (g & 1) ? oa : ea;
    const int j00 = (g + 2 * t) >> 1;

    float acc[NMT][4];
    #pragma unroll
    for (int m = 0; m < NMT; m++)
        #pragma unroll
        for (int j = 0; j < 4; j++)
            acc[m][j] = 0.f;

    u32 A0 = ap[j00];          // Av[0]
    u32 A1 = ap[j00 + 4];      // Av[1]
    #pragma unroll
    for (int u = 0; u < NDIAG; u++) {
        u32 A2 = ap[j00 + 8 * u + 8];      // Av[2u+2]
        #pragma unroll
        for (int s = 0; s < NSTEP; s++) {
            const int m = u - s;
            if (m >= 0 && m < NMT)
                mma_bf16(acc[m], A0, A1, A1, A2, Bv[s].x, Bv[s].y);
        }
        if (u < NDIAG - 1) {
            A0 = A2;
            A1 = ap[j00 + 8 * u + 12];     // Av[2u+3]
        }
    }

    // ---- Epilogue: dist = ws - 2*corr, min over all 256 rows ----
    // Thread covers k0 = 8*wid + 2t, k1 = k0+1; rows 16m+g and 16m+g+8.
    float m0 = CUDART_INF_F, m1 = CUDART_INF_F;
    #pragma unroll
    for (int m = 0; m < NMT; m++) {
        float w0 = ws[16 * m + g];
        float w1 = ws[16 * m + g + 8];
        m0 = fminf(m0, fminf(fmaf(-2.f, acc[m][0], w0), fmaf(-2.f, acc[m][2], w1)));
        m1 = fminf(m1, fminf(fmaf(-2.f, acc[m][1], w0), fmaf(-2.f, acc[m][3], w1)));
    }
    // reduce across g (lane bits 2..4); lanes 0..3 (g==0) hold results
    #pragma unroll
    for (int o = 4; o <= 16; o <<= 1) {
        m0 = fminf(m0, __shfl_xor_sync(0xffffffffu, m0, o));
        m1 = fminf(m1, __shfl_xor_sync(0xffffffffu, m1, o));
    }
    if (g == 0) {
        int k0 = wid * 8 + 2 * t;
        atomicMin((int*)&out[b * KK + k0],     __float_as_int(m0 + offs0));
        atomicMin((int*)&out[b * KK + k0 + 1], __float_as_int(m1 + offs1));
    }
}

extern "C" void kernel_launch(void* const* d_in, const int* in_sizes, int n_in,
                              void* d_out, int out_size) {
    const float* X = (const float*)d_in[0];   // (16, 8, 4096) f32
    const float* S = (const float*)d_in[1];   // (64, 128) f32
    float* out = (float*)d_out;               // (16, 64) f32

    prep_kernel<<<8, 256>>>(S, (int*)out);
    dim3 grid(NCHUNK, BB);
    shapelet_bf16_kernel<<<grid, 256>>>(X, out);
}